// round 12
// baseline (speedup 1.0000x reference)
#include <cuda_runtime.h>
#include <cuda_bf16.h>
#include <math.h>

// Problem constants
#define B    64
#define C    256
#define S    3136          // 56*56
#define S4   784           // S/4 (float4 units)
#define HID  196
#define HID4 49            // HID/4
#define KSEL 1568          // rank of first KEPT element (0-indexed kth smallest)

// K-split for GEMM1
#define KC   49
#define KCH  64            // 3136/49

// Scratch (device globals: no allocation allowed)
__device__ float g_Yp[4][B * S];        // pooled partial sums (4 c-quarters)
__device__ float g_Hpart[KC * B * HID]; // GEMM1 partials        [49][64*196]
__device__ float g_H[B * HID];          // relu(hidden)          [64,196]
__device__ float g_S[B * S];            // sigmoid outputs       [64,3136]
__device__ float g_M[B * S];            // masked row            [64,3136]
__device__ float g_scratch[128 * 8];    // prefetch sink (never read)

// ---------------------------------------------------------------------------
// K1: channel-mean pool (partial, c-split x4) FUSED with W1/W2 L2-prefetch.
// (proven R8/R9 config)  grid 912, block 256
// ---------------------------------------------------------------------------
__global__ void k_pool(const float* __restrict__ x,
                       const float* __restrict__ W1,
                       const float* __restrict__ W2) {
    int blk = blockIdx.x;
    if (blk < 128) {
        const int NF4 = (S * HID) / 4;               // 153664 float4 per matrix
        int t = blk * 256 + threadIdx.x;             // 0..32767
        float s = 0.f;
        const float4* w1 = reinterpret_cast<const float4*>(W1);
        const float4* w2 = reinterpret_cast<const float4*>(W2);
        for (int i = t; i < NF4; i += 128 * 256) {
            float4 a = __ldcg(w1 + i);
            float4 b4 = __ldcg(w2 + i);
            s += a.x + a.y + a.z + a.w + b4.x + b4.y + b4.z + b4.w;
        }
#pragma unroll
        for (int off = 16; off > 0; off >>= 1)
            s += __shfl_down_sync(0xFFFFFFFFu, s, off);
        if ((threadIdx.x & 31) == 0)
            g_scratch[blk * 8 + (threadIdx.x >> 5)] = s;
    } else {
        int id = (blk - 128) * 256 + threadIdx.x;    // 0..200703
        int q   = id / (B * S4);                     // c-quarter 0..3
        int id2 = id - q * (B * S4);                 // 0..50175
        int b = id2 / S4;
        int f = id2 - b * S4;                        // float4 column index
        const float4* xp = reinterpret_cast<const float4*>(x)
                         + (size_t)b * C * S4 + (size_t)q * 64 * S4 + f;
        float sx = 0.f, sy = 0.f, sz = 0.f, sw = 0.f;
#pragma unroll 16
        for (int c = 0; c < 64; c++) {
            float4 v = __ldcs(xp + (size_t)c * S4);
            sx += v.x; sy += v.y; sz += v.z; sw += v.w;
        }
        float4 o; o.x = sx; o.y = sy; o.z = sz; o.w = sw;
        reinterpret_cast<float4*>(g_Yp[q])[(size_t)b * S4 + f] = o;
    }
}

// ---------------------------------------------------------------------------
// K2: GEMM1 partials, 2o x 4b register tile (proven R9 config) with PDL:
// W1 smem fill (independent) runs before cudaGridDependencySynchronize();
// the g_Yp-dependent fill runs after.  grid (49 kc, 7 o-tiles), block 256.
// ---------------------------------------------------------------------------
__global__ void k_gemm1(const float* __restrict__ W1) {
    __shared__ __align__(16) float sYT[KCH * 68];  // [j][b] (17.4KB)
    __shared__ __align__(8)  float sW[KCH * 28];   // [j][o_local] (7.2KB)
    int kc = blockIdx.x;
    int o0 = blockIdx.y * 28;
    int t = threadIdx.x;
    const float inv = 1.0f / 256.0f;

    // ---- independent preamble: W1 tile -> smem (overlaps pool tail) ----
    const float4* w4 = reinterpret_cast<const float4*>(W1);
    for (int idx = t; idx < 28 * 16; idx += 256) {
        int o = idx >> 4, jq = idx & 15;
        float4 w = w4[(size_t)(o0 + o) * S4 + kc * 16 + jq];
        sW[(jq * 4 + 0) * 28 + o] = w.x;
        sW[(jq * 4 + 1) * 28 + o] = w.y;
        sW[(jq * 4 + 2) * 28 + o] = w.z;
        sW[(jq * 4 + 3) * 28 + o] = w.w;
    }

    cudaGridDependencySynchronize();   // wait for k_pool's g_Yp writes

    const float4* yp0 = reinterpret_cast<const float4*>(g_Yp[0]);
    const float4* yp1 = reinterpret_cast<const float4*>(g_Yp[1]);
    const float4* yp2 = reinterpret_cast<const float4*>(g_Yp[2]);
    const float4* yp3 = reinterpret_cast<const float4*>(g_Yp[3]);
    for (int idx = t; idx < B * 16; idx += 256) {
        int b2 = idx >> 4, jq = idx & 15;
        int gi = b2 * S4 + kc * 16 + jq;
        float4 p = yp0[gi];
        float4 q = yp1[gi];
        float4 r = yp2[gi];
        float4 u = yp3[gi];
        sYT[(jq * 4 + 0) * 68 + b2] = (p.x + q.x + r.x + u.x) * inv;
        sYT[(jq * 4 + 1) * 68 + b2] = (p.y + q.y + r.y + u.y) * inv;
        sYT[(jq * 4 + 2) * 68 + b2] = (p.z + q.z + r.z + u.z) * inv;
        sYT[(jq * 4 + 3) * 68 + b2] = (p.w + q.w + r.w + u.w) * inv;
    }
    __syncthreads();

    if (t >= 224) return;
    int og = t % 14;                     // 2 o's: og*2, og*2+1
    int bg = t / 14;                     // 0..15 -> 4 b's: bg*4..+3
    float a00 = 0.f, a01 = 0.f, a02 = 0.f, a03 = 0.f;
    float a10 = 0.f, a11 = 0.f, a12 = 0.f, a13 = 0.f;
#pragma unroll 4
    for (int j = 0; j < KCH; j++) {
        float2 w = *reinterpret_cast<const float2*>(&sW[j * 28 + og * 2]);
        float4 y = *reinterpret_cast<const float4*>(&sYT[j * 68 + bg * 4]);
        a00 = fmaf(w.x, y.x, a00); a01 = fmaf(w.x, y.y, a01);
        a02 = fmaf(w.x, y.z, a02); a03 = fmaf(w.x, y.w, a03);
        a10 = fmaf(w.y, y.x, a10); a11 = fmaf(w.y, y.y, a11);
        a12 = fmaf(w.y, y.z, a12); a13 = fmaf(w.y, y.w, a13);
    }
    int ob = o0 + og * 2;
    int base = kc * (B * HID) + (bg * 4) * HID + ob;
    g_Hpart[base + 0 * HID + 0] = a00; g_Hpart[base + 0 * HID + 1] = a10;
    g_Hpart[base + 1 * HID + 0] = a01; g_Hpart[base + 1 * HID + 1] = a11;
    g_Hpart[base + 2 * HID + 0] = a02; g_Hpart[base + 2 * HID + 1] = a12;
    g_Hpart[base + 3 * HID + 0] = a03; g_Hpart[base + 3 * HID + 1] = a13;
}

// ---------------------------------------------------------------------------
// K3: reduce 49 partials + ReLU.  2 threads per output, shuffle combine.
// grid 98, block 256.  (proven)  PDL: sync at top.
// ---------------------------------------------------------------------------
__global__ void k_redrelu() {
    cudaGridDependencySynchronize();
    int tid = blockIdx.x * 256 + threadIdx.x;
    int g   = tid >> 1;                  // output index 0..12543
    int sub = tid & 1;
    float s = 0.f;
    for (int i = sub; i < KC; i += 2)
        s += g_Hpart[i * (B * HID) + g];
    s += __shfl_xor_sync(0xFFFFFFFFu, s, 1);
    if (sub == 0)
        g_H[g] = s > 0.f ? s : 0.f;
}

// ---------------------------------------------------------------------------
// K4: GEMM2 + sigmoid, 2n x 2b register tile (proven R9 config) with PDL:
// W2 fill (independent) before the dependency sync, g_H fill after.
// grid (98, 2), block 256, 50KB dynamic smem.
// ---------------------------------------------------------------------------
__global__ void k_gemm2(const float* __restrict__ W2) {
    extern __shared__ float dyn[];
    float* sW2 = dyn;                 // [j][n_local] pitch 32
    float* sHT = dyn + HID * 32;      // [j][b_local] pitch 32
    int n0 = blockIdx.x * 32;
    int b0 = blockIdx.y * 32;
    int t = threadIdx.x;

    // ---- independent preamble: W2 tile -> smem (overlaps redrelu) ----
    const float4* w4 = reinterpret_cast<const float4*>(W2);
    for (int idx = t; idx < 32 * HID4; idx += 256) {
        int nl = idx / HID4, jq = idx - nl * HID4;
        float4 w = w4[(size_t)(n0 + nl) * HID4 + jq];
        sW2[(jq * 4 + 0) * 32 + nl] = w.x;
        sW2[(jq * 4 + 1) * 32 + nl] = w.y;
        sW2[(jq * 4 + 2) * 32 + nl] = w.z;
        sW2[(jq * 4 + 3) * 32 + nl] = w.w;
    }

    cudaGridDependencySynchronize();   // wait for k_redrelu's g_H writes

    const float4* h4 = reinterpret_cast<const float4*>(g_H);
    for (int idx = t; idx < 32 * HID4; idx += 256) {
        int b2 = idx / HID4, jq = idx - b2 * HID4;
        float4 h = h4[(size_t)(b0 + b2) * HID4 + jq];
        sHT[(jq * 4 + 0) * 32 + b2] = h.x;
        sHT[(jq * 4 + 1) * 32 + b2] = h.y;
        sHT[(jq * 4 + 2) * 32 + b2] = h.z;
        sHT[(jq * 4 + 3) * 32 + b2] = h.w;
    }
    __syncthreads();

    int ng = t & 15;                             // 2 n's
    int bg = t >> 4;                             // 2 b's
    float a00 = 0.f, a01 = 0.f, a10 = 0.f, a11 = 0.f;
#pragma unroll 4
    for (int j = 0; j < HID; j++) {
        float2 w = *reinterpret_cast<const float2*>(&sW2[j * 32 + ng * 2]);
        float2 h = *reinterpret_cast<const float2*>(&sHT[j * 32 + bg * 2]);
        a00 = fmaf(h.x, w.x, a00); a01 = fmaf(h.x, w.y, a01);
        a10 = fmaf(h.y, w.x, a10); a11 = fmaf(h.y, w.y, a11);
    }
    int b = b0 + bg * 2;
    int n = n0 + ng * 2;
    g_S[(size_t)(b + 0) * S + n + 0] = 1.0f / (1.0f + expf(-a00));
    g_S[(size_t)(b + 0) * S + n + 1] = 1.0f / (1.0f + expf(-a01));
    g_S[(size_t)(b + 1) * S + n + 0] = 1.0f / (1.0f + expf(-a10));
    g_S[(size_t)(b + 1) * S + n + 1] = 1.0f / (1.0f + expf(-a11));
}

// ---------------------------------------------------------------------------
// K5: exact rank-1568 selection per row + masking (stable-argsort semantics).
// 4-pass radix, 512 threads, WARP-AGGREGATED histogram atomics
// (__match_any_sync leader election: collapses the massive same-bin
// contention caused by sigmoid outputs sharing 2-3 exponent bytes).
// Pass 1 is fused into the g_S load loop.  grid 64, block 512.
// ---------------------------------------------------------------------------
__global__ void k_select() {
    __shared__ float sv[S];
    __shared__ unsigned int hist[256];
    __shared__ unsigned int wsum[16];
    __shared__ unsigned int sh_pref, sh_r;
    int b = blockIdx.x, t = threadIdx.x;       // t in 0..511
    int lane = t & 31, wid = t >> 5;           // 16 warps

    cudaGridDependencySynchronize();           // wait for k_gemm2's g_S

    if (t == 0) { sh_pref = 0u; sh_r = KSEL; }
    if (t < 256) hist[t] = 0u;
    __syncthreads();

    // ---- load row + pass-1 histogram (bits 31:24), warp-aggregated ----
    for (int base = 0; base < S; base += 512) {
        int i = base + t;
        bool inb = (i < S);
        float v = inb ? g_S[b * S + i] : 0.f;
        if (inb) sv[i] = v;
        unsigned u = __float_as_uint(v);
        int key = inb ? (int)(u >> 24) : (256 + lane);   // unique key if oob
        unsigned peers = __match_any_sync(0xFFFFFFFFu, key);
        if (inb && lane == (__ffs(peers) - 1))
            atomicAdd(&hist[u >> 24], (unsigned)__popc(peers));
    }
    __syncthreads();

    for (int p = 0; p < 4; p++) {
        int shift = 24 - 8 * p;
        if (p > 0) {
            // zero + rebuild histogram for this digit, warp-aggregated
            if (t < 256) hist[t] = 0u;
            __syncthreads();
            unsigned pref = sh_pref;
            unsigned hm   = 0xFFFFFFFFu << (shift + 8);
            for (int base = 0; base < S; base += 512) {
                int i = base + t;
                bool ok = (i < S);
                unsigned u = ok ? __float_as_uint(sv[i]) : 0u;
                ok = ok && ((u & hm) == pref);
                int bin = (u >> shift) & 255;
                int key = ok ? bin : (256 + lane);
                unsigned peers = __match_any_sync(0xFFFFFFFFu, key);
                if (ok && lane == (__ffs(peers) - 1))
                    atomicAdd(&hist[bin], (unsigned)__popc(peers));
            }
            __syncthreads();
        }
        // scan 256 bins (512 threads; v=0 for t>=256) + pick the bin
        unsigned v = (t < 256) ? hist[t] : 0u;
        unsigned x = v;
#pragma unroll
        for (int off = 1; off < 32; off <<= 1) {
            unsigned y = __shfl_up_sync(0xFFFFFFFFu, x, off);
            if (lane >= off) x += y;
        }
        if (lane == 31) wsum[wid] = x;
        __syncthreads();
        if (t < 16) {
            unsigned s = wsum[t];
#pragma unroll
            for (int off = 1; off < 16; off <<= 1) {
                unsigned y = __shfl_up_sync(0xFFFFu, s, off);
                if (t >= off) s += y;
            }
            wsum[t] = s;
        }
        __syncthreads();
        unsigned r    = sh_r;
        unsigned incl = x + (wid ? wsum[wid - 1] : 0u);
        unsigned excl = incl - v;
        if (v > 0u && r >= excl && r < incl) {   // exactly one thread (t<256)
            sh_pref = sh_pref | ((unsigned)t << shift);
            sh_r    = r - excl;
        }
        __syncthreads();
    }
    unsigned T    = sh_pref;
    unsigned rfin = sh_r;

    int lo = (t * S) >> 9;
    int hi = ((t + 1) * S) >> 9;
    unsigned cnt = 0;
    for (int i = lo; i < hi; i++)
        cnt += (__float_as_uint(sv[i]) == T) ? 1u : 0u;
    unsigned x = cnt;
#pragma unroll
    for (int off = 1; off < 32; off <<= 1) {
        unsigned y = __shfl_up_sync(0xFFFFFFFFu, x, off);
        if (lane >= off) x += y;
    }
    if (lane == 31) wsum[wid] = x;
    __syncthreads();
    if (t < 16) {
        unsigned s = wsum[t];
#pragma unroll
        for (int off = 1; off < 16; off <<= 1) {
            unsigned y = __shfl_up_sync(0xFFFFu, s, off);
            if (t >= off) s += y;
        }
        wsum[t] = s;
    }
    __syncthreads();
    unsigned e = x - cnt + (wid ? wsum[wid - 1] : 0u);
    for (int i = lo; i < hi; i++) {
        unsigned u = __float_as_uint(sv[i]);
        float val = sv[i];
        if (u < T) val = 0.f;
        else if (u == T) { if (e < rfin) val = 0.f; e++; }
        g_M[b * S + i] = val;
    }
}

// ---------------------------------------------------------------------------
// K6: broadcast masked row over 256 planes.  grid 1568, block 256. (proven)
// PDL: sync at top (gains launch-ramp overlap with k_select).
// ---------------------------------------------------------------------------
__global__ void k_bcast(float* __restrict__ out) {
    cudaGridDependencySynchronize();           // wait for k_select's g_M
    int id = blockIdx.x * 256 + threadIdx.x;     // 0 .. 64*8*784-1
    int f  = id % S4;
    int bc = id / S4;                            // b*8 + cg
    int cg = bc & 7;
    int b  = bc >> 3;
    float4 v = __ldcg(reinterpret_cast<const float4*>(g_M) + (size_t)b * S4 + f);
    float4* op = reinterpret_cast<float4*>(out)
               + (size_t)(b * C + cg * 32) * S4 + f;
#pragma unroll 8
    for (int c = 0; c < 32; c++)
        __stcs(op + (size_t)c * S4, v);
}

// ---------------------------------------------------------------------------
// Helper: launch with programmatic stream serialization (PDL)
// ---------------------------------------------------------------------------
template <typename... Args>
static void launch_pdl(void (*kern)(Args...), dim3 grid, dim3 block,
                       size_t smem, Args... args) {
    cudaLaunchConfig_t cfg = {};
    cfg.gridDim = grid;
    cfg.blockDim = block;
    cfg.dynamicSmemBytes = smem;
    cfg.stream = 0;
    cudaLaunchAttribute attr[1];
    attr[0].id = cudaLaunchAttributeProgrammaticStreamSerialization;
    attr[0].val.programmaticStreamSerializationAllowed = 1;
    cfg.attrs = attr;
    cfg.numAttrs = 1;
    cudaLaunchKernelEx(&cfg, kern, args...);
}

// ---------------------------------------------------------------------------
extern "C" void kernel_launch(void* const* d_in, const int* in_sizes, int n_in,
                              void* d_out, int out_size) {
    const float* x  = (const float*)d_in[0];
    const float* W1 = (const float*)d_in[1];
    const float* W2 = (const float*)d_in[2];
    float* out = (float*)d_out;

    static int smem_set = 0;
    if (!smem_set) {
        cudaFuncSetAttribute(k_gemm2, cudaFuncAttributeMaxDynamicSharedMemorySize,
                             2 * HID * 32 * (int)sizeof(float));
        smem_set = 1;
    }

    k_pool<<<912, 256>>>(x, W1, W2);
    launch_pdl(k_gemm1,   dim3(KC, 7), dim3(256), 0, W1);
    launch_pdl(k_redrelu, dim3(98),    dim3(256), (size_t)0);
    launch_pdl(k_gemm2,   dim3(98, 2), dim3(256), 2 * HID * 32 * sizeof(float), W2);
    launch_pdl(k_select,  dim3(B),     dim3(512), (size_t)0);
    launch_pdl(k_bcast,   dim3(1568),  dim3(256), 0, out);
}

// round 13
// speedup vs baseline: 1.4829x; 1.4829x over previous
#include <cuda_runtime.h>
#include <cuda_bf16.h>
#include <math.h>

// Problem constants
#define B    64
#define C    256
#define S    3136          // 56*56
#define S4   784           // S/4 (float4 units)
#define HID  196
#define HID4 49            // HID/4
#define KSEL 1568          // rank of first KEPT element (0-indexed kth smallest)

// K-split for GEMM1
#define KC   49
#define KCH  64            // 3136/49

// Scratch (device globals: no allocation allowed)
__device__ float g_Yp[8][B * S];        // pooled partial sums (8 c-slices)
__device__ float g_Hpart[KC * B * HID]; // GEMM1 partials        [49][64*196]
__device__ float g_H[B * HID];          // relu(hidden)          [64,196]
__device__ float g_S[B * S];            // sigmoid outputs       [64,3136]
__device__ float g_M[B * S];            // masked row            [64,3136]
__device__ float g_scratch[128 * 8];    // prefetch sink (never read)

// ---------------------------------------------------------------------------
// K1: channel-mean pool (partial, c-split x8) FUSED with W1/W2 L2-prefetch.
// Blocks 0..127:    warm W1+W2 (4.9MB) into L2 via __ldcg (wave-1 scheduled).
// Blocks 128..1695: 1568 balanced pool blocks; each thread sums one float4
//   column over 32 channels (__ldcs evict-first) into g_Yp[slice].
// grid 1696, block 256
// ---------------------------------------------------------------------------
__global__ void k_pool(const float* __restrict__ x,
                       const float* __restrict__ W1,
                       const float* __restrict__ W2) {
    int blk = blockIdx.x;
    if (blk < 128) {
        const int NF4 = (S * HID) / 4;               // 153664 float4 per matrix
        int t = blk * 256 + threadIdx.x;             // 0..32767
        float s = 0.f;
        const float4* w1 = reinterpret_cast<const float4*>(W1);
        const float4* w2 = reinterpret_cast<const float4*>(W2);
        for (int i = t; i < NF4; i += 128 * 256) {
            float4 a = __ldcg(w1 + i);
            float4 b4 = __ldcg(w2 + i);
            s += a.x + a.y + a.z + a.w + b4.x + b4.y + b4.z + b4.w;
        }
#pragma unroll
        for (int off = 16; off > 0; off >>= 1)
            s += __shfl_down_sync(0xFFFFFFFFu, s, off);
        if ((threadIdx.x & 31) == 0)
            g_scratch[blk * 8 + (threadIdx.x >> 5)] = s;
    } else {
        int id = (blk - 128) * 256 + threadIdx.x;    // 0..401407
        int q   = id / (B * S4);                     // c-slice 0..7
        int id2 = id - q * (B * S4);                 // 0..50175
        int b = id2 / S4;
        int f = id2 - b * S4;                        // float4 column index
        const float4* xp = reinterpret_cast<const float4*>(x)
                         + (size_t)b * C * S4 + (size_t)q * 32 * S4 + f;
        float sx = 0.f, sy = 0.f, sz = 0.f, sw = 0.f;
#pragma unroll 16
        for (int c = 0; c < 32; c++) {
            float4 v = __ldcs(xp + (size_t)c * S4);
            sx += v.x; sy += v.y; sz += v.z; sw += v.w;
        }
        float4 o; o.x = sx; o.y = sy; o.z = sz; o.w = sw;
        reinterpret_cast<float4*>(g_Yp[q])[(size_t)b * S4 + f] = o;
    }
}

// ---------------------------------------------------------------------------
// K2: GEMM1 partials, 2o x 4b register tile (proven R9/R11 config) with PDL:
// W1 smem fill (independent) runs before cudaGridDependencySynchronize();
// the g_Yp-dependent fill (8 partial slices) runs after.
// grid (49 kc, 7 o-tiles), block 256.
// ---------------------------------------------------------------------------
__global__ void k_gemm1(const float* __restrict__ W1) {
    __shared__ __align__(16) float sYT[KCH * 68];  // [j][b] (17.4KB)
    __shared__ __align__(8)  float sW[KCH * 28];   // [j][o_local] (7.2KB)
    int kc = blockIdx.x;
    int o0 = blockIdx.y * 28;
    int t = threadIdx.x;
    const float inv = 1.0f / 256.0f;

    // ---- independent preamble: W1 tile -> smem (overlaps pool tail) ----
    const float4* w4 = reinterpret_cast<const float4*>(W1);
    for (int idx = t; idx < 28 * 16; idx += 256) {
        int o = idx >> 4, jq = idx & 15;
        float4 w = w4[(size_t)(o0 + o) * S4 + kc * 16 + jq];
        sW[(jq * 4 + 0) * 28 + o] = w.x;
        sW[(jq * 4 + 1) * 28 + o] = w.y;
        sW[(jq * 4 + 2) * 28 + o] = w.z;
        sW[(jq * 4 + 3) * 28 + o] = w.w;
    }

    cudaGridDependencySynchronize();   // wait for k_pool's g_Yp writes

    for (int idx = t; idx < B * 16; idx += 256) {
        int b2 = idx >> 4, jq = idx & 15;
        int gi = b2 * S4 + kc * 16 + jq;
        float ax = 0.f, ay = 0.f, az = 0.f, aw = 0.f;
#pragma unroll
        for (int q = 0; q < 8; q++) {
            float4 v = reinterpret_cast<const float4*>(g_Yp[q])[gi];
            ax += v.x; ay += v.y; az += v.z; aw += v.w;
        }
        sYT[(jq * 4 + 0) * 68 + b2] = ax * inv;
        sYT[(jq * 4 + 1) * 68 + b2] = ay * inv;
        sYT[(jq * 4 + 2) * 68 + b2] = az * inv;
        sYT[(jq * 4 + 3) * 68 + b2] = aw * inv;
    }
    __syncthreads();

    if (t >= 224) return;
    int og = t % 14;                     // 2 o's: og*2, og*2+1
    int bg = t / 14;                     // 0..15 -> 4 b's: bg*4..+3
    float a00 = 0.f, a01 = 0.f, a02 = 0.f, a03 = 0.f;
    float a10 = 0.f, a11 = 0.f, a12 = 0.f, a13 = 0.f;
#pragma unroll 4
    for (int j = 0; j < KCH; j++) {
        float2 w = *reinterpret_cast<const float2*>(&sW[j * 28 + og * 2]);
        float4 y = *reinterpret_cast<const float4*>(&sYT[j * 68 + bg * 4]);
        a00 = fmaf(w.x, y.x, a00); a01 = fmaf(w.x, y.y, a01);
        a02 = fmaf(w.x, y.z, a02); a03 = fmaf(w.x, y.w, a03);
        a10 = fmaf(w.y, y.x, a10); a11 = fmaf(w.y, y.y, a11);
        a12 = fmaf(w.y, y.z, a12); a13 = fmaf(w.y, y.w, a13);
    }
    int ob = o0 + og * 2;
    int base = kc * (B * HID) + (bg * 4) * HID + ob;
    g_Hpart[base + 0 * HID + 0] = a00; g_Hpart[base + 0 * HID + 1] = a10;
    g_Hpart[base + 1 * HID + 0] = a01; g_Hpart[base + 1 * HID + 1] = a11;
    g_Hpart[base + 2 * HID + 0] = a02; g_Hpart[base + 2 * HID + 1] = a12;
    g_Hpart[base + 3 * HID + 0] = a03; g_Hpart[base + 3 * HID + 1] = a13;
}

// ---------------------------------------------------------------------------
// K3: reduce 49 partials + ReLU.  2 threads per output, shuffle combine.
// grid 98, block 256.  (proven)  PDL: sync at top.
// ---------------------------------------------------------------------------
__global__ void k_redrelu() {
    cudaGridDependencySynchronize();
    int tid = blockIdx.x * 256 + threadIdx.x;
    int g   = tid >> 1;                  // output index 0..12543
    int sub = tid & 1;
    float s = 0.f;
    for (int i = sub; i < KC; i += 2)
        s += g_Hpart[i * (B * HID) + g];
    s += __shfl_xor_sync(0xFFFFFFFFu, s, 1);
    if (sub == 0)
        g_H[g] = s > 0.f ? s : 0.f;
}

// ---------------------------------------------------------------------------
// K4: GEMM2 + sigmoid, 2n x 2b register tile (proven R9/R11 config) with PDL:
// W2 fill (independent) before the dependency sync, g_H fill after.
// grid (98, 2), block 256, 50KB dynamic smem.
// ---------------------------------------------------------------------------
__global__ void k_gemm2(const float* __restrict__ W2) {
    extern __shared__ float dyn[];
    float* sW2 = dyn;                 // [j][n_local] pitch 32
    float* sHT = dyn + HID * 32;      // [j][b_local] pitch 32
    int n0 = blockIdx.x * 32;
    int b0 = blockIdx.y * 32;
    int t = threadIdx.x;

    // ---- independent preamble: W2 tile -> smem (overlaps redrelu) ----
    const float4* w4 = reinterpret_cast<const float4*>(W2);
    for (int idx = t; idx < 32 * HID4; idx += 256) {
        int nl = idx / HID4, jq = idx - nl * HID4;
        float4 w = w4[(size_t)(n0 + nl) * HID4 + jq];
        sW2[(jq * 4 + 0) * 32 + nl] = w.x;
        sW2[(jq * 4 + 1) * 32 + nl] = w.y;
        sW2[(jq * 4 + 2) * 32 + nl] = w.z;
        sW2[(jq * 4 + 3) * 32 + nl] = w.w;
    }

    cudaGridDependencySynchronize();   // wait for k_redrelu's g_H writes

    const float4* h4 = reinterpret_cast<const float4*>(g_H);
    for (int idx = t; idx < 32 * HID4; idx += 256) {
        int b2 = idx / HID4, jq = idx - b2 * HID4;
        float4 h = h4[(size_t)(b0 + b2) * HID4 + jq];
        sHT[(jq * 4 + 0) * 32 + b2] = h.x;
        sHT[(jq * 4 + 1) * 32 + b2] = h.y;
        sHT[(jq * 4 + 2) * 32 + b2] = h.z;
        sHT[(jq * 4 + 3) * 32 + b2] = h.w;
    }
    __syncthreads();

    int ng = t & 15;                             // 2 n's
    int bg = t >> 4;                             // 2 b's
    float a00 = 0.f, a01 = 0.f, a10 = 0.f, a11 = 0.f;
#pragma unroll 4
    for (int j = 0; j < HID; j++) {
        float2 w = *reinterpret_cast<const float2*>(&sW2[j * 32 + ng * 2]);
        float2 h = *reinterpret_cast<const float2*>(&sHT[j * 32 + bg * 2]);
        a00 = fmaf(h.x, w.x, a00); a01 = fmaf(h.x, w.y, a01);
        a10 = fmaf(h.y, w.x, a10); a11 = fmaf(h.y, w.y, a11);
    }
    int b = b0 + bg * 2;
    int n = n0 + ng * 2;
    g_S[(size_t)(b + 0) * S + n + 0] = 1.0f / (1.0f + expf(-a00));
    g_S[(size_t)(b + 0) * S + n + 1] = 1.0f / (1.0f + expf(-a01));
    g_S[(size_t)(b + 1) * S + n + 0] = 1.0f / (1.0f + expf(-a10));
    g_S[(size_t)(b + 1) * S + n + 1] = 1.0f / (1.0f + expf(-a11));
}

// ---------------------------------------------------------------------------
// K5: exact rank-1568 selection per row + masking (stable-argsort semantics).
// 4-pass radix, 512 threads (proven R8/R11 config).  PDL: sync at top.
// grid 64, block 512.
// ---------------------------------------------------------------------------
__global__ void k_select() {
    __shared__ float sv[S];
    __shared__ unsigned int hist[256];
    __shared__ unsigned int wsum[16];
    __shared__ unsigned int sh_pref, sh_r;
    int b = blockIdx.x, t = threadIdx.x;       // t in 0..511
    int lane = t & 31, wid = t >> 5;           // 16 warps

    cudaGridDependencySynchronize();           // wait for k_gemm2's g_S

    for (int i = t; i < S; i += 512) sv[i] = g_S[b * S + i];
    if (t == 0) { sh_pref = 0u; sh_r = KSEL; }
    __syncthreads();

    for (int shift = 24; shift >= 0; shift -= 8) {
        if (t < 256) hist[t] = 0u;
        __syncthreads();
        unsigned pref = sh_pref;
        unsigned r    = sh_r;
        unsigned hm   = (shift == 24) ? 0u : (0xFFFFFFFFu << (shift + 8));
        for (int i = t; i < S; i += 512) {
            unsigned u = __float_as_uint(sv[i]);
            if ((u & hm) == pref) atomicAdd(&hist[(u >> shift) & 255], 1u);
        }
        __syncthreads();
        unsigned v = (t < 256) ? hist[t] : 0u;
        unsigned x = v;
#pragma unroll
        for (int off = 1; off < 32; off <<= 1) {
            unsigned y = __shfl_up_sync(0xFFFFFFFFu, x, off);
            if (lane >= off) x += y;
        }
        if (lane == 31) wsum[wid] = x;
        __syncthreads();
        if (t < 16) {
            unsigned s = wsum[t];
#pragma unroll
            for (int off = 1; off < 16; off <<= 1) {
                unsigned y = __shfl_up_sync(0xFFFFu, s, off);
                if (t >= off) s += y;
            }
            wsum[t] = s;
        }
        __syncthreads();
        unsigned incl = x + (wid ? wsum[wid - 1] : 0u);
        unsigned excl = incl - v;
        if (v > 0u && r >= excl && r < incl) {   // exactly one thread (t<256)
            sh_pref = pref | ((unsigned)t << shift);
            sh_r    = r - excl;
        }
        __syncthreads();
    }
    unsigned T    = sh_pref;
    unsigned rfin = sh_r;

    int lo = (t * S) >> 9;
    int hi = ((t + 1) * S) >> 9;
    unsigned cnt = 0;
    for (int i = lo; i < hi; i++)
        cnt += (__float_as_uint(sv[i]) == T) ? 1u : 0u;
    unsigned x = cnt;
#pragma unroll
    for (int off = 1; off < 32; off <<= 1) {
        unsigned y = __shfl_up_sync(0xFFFFFFFFu, x, off);
        if (lane >= off) x += y;
    }
    if (lane == 31) wsum[wid] = x;
    __syncthreads();
    if (t < 16) {
        unsigned s = wsum[t];
#pragma unroll
        for (int off = 1; off < 16; off <<= 1) {
            unsigned y = __shfl_up_sync(0xFFFFu, s, off);
            if (t >= off) s += y;
        }
        wsum[t] = s;
    }
    __syncthreads();
    unsigned e = x - cnt + (wid ? wsum[wid - 1] : 0u);
    for (int i = lo; i < hi; i++) {
        unsigned u = __float_as_uint(sv[i]);
        float val = sv[i];
        if (u < T) val = 0.f;
        else if (u == T) { if (e < rfin) val = 0.f; e++; }
        g_M[b * S + i] = val;
    }
}

// ---------------------------------------------------------------------------
// K6: broadcast masked row over 256 planes.  grid 1568, block 256. (proven)
// PDL: sync at top (gains launch-ramp overlap with k_select).
// ---------------------------------------------------------------------------
__global__ void k_bcast(float* __restrict__ out) {
    cudaGridDependencySynchronize();           // wait for k_select's g_M
    int id = blockIdx.x * 256 + threadIdx.x;     // 0 .. 64*8*784-1
    int f  = id % S4;
    int bc = id / S4;                            // b*8 + cg
    int cg = bc & 7;
    int b  = bc >> 3;
    float4 v = __ldcg(reinterpret_cast<const float4*>(g_M) + (size_t)b * S4 + f);
    float4* op = reinterpret_cast<float4*>(out)
               + (size_t)(b * C + cg * 32) * S4 + f;
#pragma unroll 8
    for (int c = 0; c < 32; c++)
        __stcs(op + (size_t)c * S4, v);
}

// ---------------------------------------------------------------------------
// Helper: launch with programmatic stream serialization (PDL)
// ---------------------------------------------------------------------------
template <typename... Args>
static void launch_pdl(void (*kern)(Args...), dim3 grid, dim3 block,
                       size_t smem, Args... args) {
    cudaLaunchConfig_t cfg = {};
    cfg.gridDim = grid;
    cfg.blockDim = block;
    cfg.dynamicSmemBytes = smem;
    cfg.stream = 0;
    cudaLaunchAttribute attr[1];
    attr[0].id = cudaLaunchAttributeProgrammaticStreamSerialization;
    attr[0].val.programmaticStreamSerializationAllowed = 1;
    cfg.attrs = attr;
    cfg.numAttrs = 1;
    cudaLaunchKernelEx(&cfg, kern, args...);
}

// ---------------------------------------------------------------------------
extern "C" void kernel_launch(void* const* d_in, const int* in_sizes, int n_in,
                              void* d_out, int out_size) {
    const float* x  = (const float*)d_in[0];
    const float* W1 = (const float*)d_in[1];
    const float* W2 = (const float*)d_in[2];
    float* out = (float*)d_out;

    static int smem_set = 0;
    if (!smem_set) {
        cudaFuncSetAttribute(k_gemm2, cudaFuncAttributeMaxDynamicSharedMemorySize,
                             2 * HID * 32 * (int)sizeof(float));
        smem_set = 1;
    }

    k_pool<<<1696, 256>>>(x, W1, W2);
    launch_pdl(k_gemm1,   dim3(KC, 7), dim3(256), 0, W1);
    launch_pdl(k_redrelu, dim3(98),    dim3(256), (size_t)0);
    launch_pdl(k_gemm2,   dim3(98, 2), dim3(256), 2 * HID * 32 * sizeof(float), W2);
    launch_pdl(k_select,  dim3(B),     dim3(512), (size_t)0);
    launch_pdl(k_bcast,   dim3(1568),  dim3(256), 0, out);
}